// round 5
// baseline (speedup 1.0000x reference)
#include <cuda_runtime.h>
#include <cuda_bf16.h>

#define D      1024
#define BATCH  64
#define KV     4096
#define KV1    4097
#define NCHUNK 16

// Scratch (no allocations allowed) ------------------------------------------
__device__ float g_cur[BATCH * D];
__device__ float g_q[BATCH * D];
__device__ float g_knew[BATCH * D];
__device__ float g_vnew[BATCH * D];
__device__ float g_scores[BATCH * KV1];
__device__ float g_attn[BATCH * D];

// ---------------------------------------------------------------------------
__global__ void init_kernel(const int* __restrict__ x, const float* __restrict__ emb,
                            const float* __restrict__ bq, const float* __restrict__ bk,
                            const float* __restrict__ bv, const float* __restrict__ bo,
                            float* __restrict__ out) {
    int b = blockIdx.x;
    int row = x[b];
    for (int i = threadIdx.x; i < D; i += blockDim.x) {
        g_cur[b * D + i]  = emb[(size_t)row * D + i];
        g_q[b * D + i]    = bq[i];
        g_knew[b * D + i] = bk[i];
        g_vnew[b * D + i] = bv[i];
        g_attn[b * D + i] = 0.f;
        out[b * D + i]    = bo[i];
    }
}

// ---------------------------------------------------------------------------
// Split-K GEMM: C[b,e] += sum_{k in 128-slice} A[b,k] * W[e,k]
// mode 0: A=g_cur, z selects (Wq->g_q, Wk->g_knew, Wv->g_vnew), grid (16,8,3)
// mode 1: A=g_attn, W=Wa, C=Cext, grid (16,8)
__global__ void gemm_splitk(int mode, const float* __restrict__ Wa,
                            const float* __restrict__ Wb, const float* __restrict__ Wc,
                            float* __restrict__ Cext) {
    const float* A = (mode == 0) ? g_cur : g_attn;
    const float* W = (mode == 0)
        ? (blockIdx.z == 0 ? Wa : blockIdx.z == 1 ? Wb : Wc) : Wa;
    float* C = (mode == 0)
        ? (blockIdx.z == 0 ? g_q : blockIdx.z == 1 ? g_knew : g_vnew) : Cext;

    __shared__ float As[64][65];
    __shared__ float Ws[64][65];
    const int e0 = blockIdx.x * 64;
    const int kbase = blockIdx.y * 128;          // K-slice of 128
    const int tid = threadIdx.x;
    const int ty = tid >> 4, tx = tid & 15;
    float acc[4][4] = {};

    for (int k0 = kbase; k0 < kbase + 128; k0 += 64) {
        for (int i = tid; i < 1024; i += 256) {
            int row = i >> 4;
            int c4  = (i & 15) * 4;
            float4 a = *(const float4*)(A + (size_t)row * D + k0 + c4);
            As[row][c4 + 0] = a.x; As[row][c4 + 1] = a.y;
            As[row][c4 + 2] = a.z; As[row][c4 + 3] = a.w;
            float4 w = *(const float4*)(W + (size_t)(e0 + row) * D + k0 + c4);
            Ws[row][c4 + 0] = w.x; Ws[row][c4 + 1] = w.y;
            Ws[row][c4 + 2] = w.z; Ws[row][c4 + 3] = w.w;
        }
        __syncthreads();
        #pragma unroll
        for (int kk = 0; kk < 64; kk++) {
            float av[4], wv[4];
            #pragma unroll
            for (int i = 0; i < 4; i++) av[i] = As[ty * 4 + i][kk];
            #pragma unroll
            for (int j = 0; j < 4; j++) wv[j] = Ws[tx * 4 + j][kk];
            #pragma unroll
            for (int i = 0; i < 4; i++)
                #pragma unroll
                for (int j = 0; j < 4; j++) acc[i][j] += av[i] * wv[j];
        }
        __syncthreads();
    }
    #pragma unroll
    for (int i = 0; i < 4; i++) {
        int b = ty * 4 + i;
        #pragma unroll
        for (int j = 0; j < 4; j++) {
            int e = e0 + tx * 4 + j;
            atomicAdd(&C[(size_t)b * D + e], acc[i][j]);
        }
    }
}

// ---------------------------------------------------------------------------
// Fused: scores[b,s] = (q[b] . k[b,s]) / 32  AND  k_out[b,s,:] = k[b,s,:]
// One warp per s-row; 16 rows per 512-thread block.
// All 8 LDG.128 issued before any compute/store (MLP=8).
__global__ void scores_copy_kernel(const float* __restrict__ prev_k,
                                   float* __restrict__ k_out) {
    int b = blockIdx.x;
    __shared__ float4 qs[D / 4];
    for (int i = threadIdx.x; i < D / 4; i += blockDim.x)
        qs[i] = ((const float4*)(g_q + b * D))[i];
    __syncthreads();

    int s = blockIdx.y * 16 + (threadIdx.x >> 5);
    if (s > KV) return;
    int lane = threadIdx.x & 31;

    const float4* src = (s < KV)
        ? (const float4*)(prev_k + ((size_t)b * KV + s) * D)
        : (const float4*)(g_knew + b * D);
    float4* dst = (float4*)(k_out + ((size_t)b * KV1 + s) * D);

    float4 kv[8];
    #pragma unroll
    for (int i = 0; i < 8; i++) kv[i] = __ldcs(src + lane + i * 32);

    float acc = 0.f;
    #pragma unroll
    for (int i = 0; i < 8; i++) {
        float4 qv = qs[lane + i * 32];
        acc += kv[i].x * qv.x + kv[i].y * qv.y + kv[i].z * qv.z + kv[i].w * qv.w;
        __stcs(dst + lane + i * 32, kv[i]);
    }
    #pragma unroll
    for (int o = 16; o; o >>= 1) acc += __shfl_xor_sync(0xffffffffu, acc, o);
    if (lane == 0) g_scores[b * KV1 + s] = acc * 0.03125f;   // 1/sqrt(1024)
}

// ---------------------------------------------------------------------------
// Softmax over 4097 scores per row. 1024 threads, 4 elems/thread.
__global__ void softmax_kernel() {
    int b = blockIdx.x;
    float* sc = g_scores + b * KV1;
    __shared__ float red[32];
    int tid = threadIdx.x;

    float m = -1e30f;
    for (int i = tid; i < KV1; i += 1024) m = fmaxf(m, sc[i]);
    #pragma unroll
    for (int o = 16; o; o >>= 1) m = fmaxf(m, __shfl_xor_sync(0xffffffffu, m, o));
    if ((tid & 31) == 0) red[tid >> 5] = m;
    __syncthreads();
    if (tid < 32) {
        float v = red[tid];
        #pragma unroll
        for (int o = 16; o; o >>= 1) v = fmaxf(v, __shfl_xor_sync(0xffffffffu, v, o));
        if (tid == 0) red[0] = v;
    }
    __syncthreads();
    m = red[0];
    __syncthreads();

    float sum = 0.f;
    for (int i = tid; i < KV1; i += 1024) {
        float e = __expf(sc[i] - m);
        sc[i] = e;
        sum += e;
    }
    #pragma unroll
    for (int o = 16; o; o >>= 1) sum += __shfl_xor_sync(0xffffffffu, sum, o);
    if ((tid & 31) == 0) red[tid >> 5] = sum;
    __syncthreads();
    if (tid < 32) {
        float v = red[tid];
        #pragma unroll
        for (int o = 16; o; o >>= 1) v += __shfl_xor_sync(0xffffffffu, v, o);
        if (tid == 0) red[0] = v;
    }
    __syncthreads();
    float inv = 1.0f / red[0];
    for (int i = tid; i < KV1; i += 1024) sc[i] *= inv;
}

// ---------------------------------------------------------------------------
// Fused: attn[b,d] += sum_{s in chunk} probs[b,s]*v[b,s,d]  AND copy v rows.
// Block = (b, 256-row s-chunk); 256 threads; 8-deep load batches (MLP=8).
__global__ void attn_copy_kernel(const float* __restrict__ prev_v,
                                 float* __restrict__ v_out) {
    int b = blockIdx.x;
    int s0 = blockIdx.y * 256;
    int t = threadIdx.x;
    const float* p = g_scores + b * KV1;
    __shared__ float ps[256];
    ps[t] = p[s0 + t];
    __syncthreads();

    const float4* vbase = (const float4*)(prev_v + (size_t)b * KV * D) + t;
    float4* obase = (float4*)(v_out + (size_t)b * KV1 * D) + t;

    float4 acc = make_float4(0.f, 0.f, 0.f, 0.f);
    for (int s = 0; s < 256; s += 8) {
        float4 val[8];
        #pragma unroll
        for (int j = 0; j < 8; j++)
            val[j] = __ldcs(vbase + (size_t)(s0 + s + j) * (D / 4));
        #pragma unroll
        for (int j = 0; j < 8; j++) {
            float w = ps[s + j];
            acc.x += w * val[j].x; acc.y += w * val[j].y;
            acc.z += w * val[j].z; acc.w += w * val[j].w;
            __stcs(obase + (size_t)(s0 + s + j) * (D / 4), val[j]);
        }
    }
    if (blockIdx.y == NCHUNK - 1) {              // new row s = 4096
        float4 val = ((const float4*)(g_vnew + b * D))[t];
        float w = p[KV];
        acc.x += w * val.x; acc.y += w * val.y;
        acc.z += w * val.z; acc.w += w * val.w;
        __stcs(obase + (size_t)KV * (D / 4), val);
    }
    float* ga = g_attn + b * D + t * 4;
    atomicAdd(ga + 0, acc.x);
    atomicAdd(ga + 1, acc.y);
    atomicAdd(ga + 2, acc.z);
    atomicAdd(ga + 3, acc.w);
}

// ---------------------------------------------------------------------------
extern "C" void kernel_launch(void* const* d_in, const int* in_sizes, int n_in,
                              void* d_out, int out_size) {
    const int*   x      = (const int*)d_in[0];
    const float* prev_k = (const float*)d_in[1];
    const float* prev_v = (const float*)d_in[2];
    const float* emb    = (const float*)d_in[3];
    const float* Wq     = (const float*)d_in[4];
    const float* bq     = (const float*)d_in[5];
    const float* Wk     = (const float*)d_in[6];
    const float* bk     = (const float*)d_in[7];
    const float* Wv     = (const float*)d_in[8];
    const float* bv     = (const float*)d_in[9];
    const float* Wo     = (const float*)d_in[10];
    const float* bo     = (const float*)d_in[11];

    float* out   = (float*)d_out;                       // (64, 1, 1024)
    float* k_out = out + (size_t)BATCH * D;             // (64, 4097, 1024)
    float* v_out = k_out + (size_t)BATCH * KV1 * D;     // (64, 4097, 1024)

    init_kernel<<<BATCH, 256>>>(x, emb, bq, bk, bv, bo, out);
    gemm_splitk<<<dim3(16, 8, 3), 256>>>(0, Wq, Wk, Wv, nullptr);
    scores_copy_kernel<<<dim3(BATCH, 257), 512>>>(prev_k, k_out);
    softmax_kernel<<<BATCH, 1024>>>();
    attn_copy_kernel<<<dim3(BATCH, NCHUNK), 256>>>(prev_v, v_out);
    gemm_splitk<<<dim3(16, 8, 1), 256>>>(1, Wo, nullptr, nullptr, out);
}

// round 6
// speedup vs baseline: 1.0020x; 1.0020x over previous
#include <cuda_runtime.h>
#include <cuda_bf16.h>

#define D      1024
#define BATCH  64
#define KV     4096
#define KV1    4097
#define NCHUNK 16

// Scratch (no allocations allowed) ------------------------------------------
__device__ float g_cur[BATCH * D];
__device__ float g_q[BATCH * D];
__device__ float g_knew[BATCH * D];
__device__ float g_vnew[BATCH * D];
__device__ float g_scores[BATCH * KV1];
__device__ float g_attn[BATCH * D];

// ---------------------------------------------------------------------------
__global__ void init_kernel(const int* __restrict__ x, const float* __restrict__ emb,
                            const float* __restrict__ bq, const float* __restrict__ bk,
                            const float* __restrict__ bv, const float* __restrict__ bo,
                            float* __restrict__ out) {
    int b = blockIdx.x;
    int row = x[b];
    for (int i = threadIdx.x; i < D; i += blockDim.x) {
        g_cur[b * D + i]  = emb[(size_t)row * D + i];
        g_q[b * D + i]    = bq[i];
        g_knew[b * D + i] = bk[i];
        g_vnew[b * D + i] = bv[i];
        g_attn[b * D + i] = 0.f;
        out[b * D + i]    = bo[i];
    }
}

// ---------------------------------------------------------------------------
// Split-K GEMM: C[b,e] += sum_{k in 128-slice} A[b,k] * W[e,k]
// mode 0: A=g_cur, z selects (Wq->g_q, Wk->g_knew, Wv->g_vnew), grid (16,8,3)
// mode 1: A=g_attn, W=Wa, C=Cext, grid (16,8)
__global__ void gemm_splitk(int mode, const float* __restrict__ Wa,
                            const float* __restrict__ Wb, const float* __restrict__ Wc,
                            float* __restrict__ Cext) {
    const float* A = (mode == 0) ? g_cur : g_attn;
    const float* W = (mode == 0)
        ? (blockIdx.z == 0 ? Wa : blockIdx.z == 1 ? Wb : Wc) : Wa;
    float* C = (mode == 0)
        ? (blockIdx.z == 0 ? g_q : blockIdx.z == 1 ? g_knew : g_vnew) : Cext;

    __shared__ float As[64][65];
    __shared__ float Ws[64][65];
    const int e0 = blockIdx.x * 64;
    const int kbase = blockIdx.y * 128;          // K-slice of 128
    const int tid = threadIdx.x;
    const int ty = tid >> 4, tx = tid & 15;
    float acc[4][4] = {};

    for (int k0 = kbase; k0 < kbase + 128; k0 += 64) {
        for (int i = tid; i < 1024; i += 256) {
            int row = i >> 4;
            int c4  = (i & 15) * 4;
            float4 a = *(const float4*)(A + (size_t)row * D + k0 + c4);
            As[row][c4 + 0] = a.x; As[row][c4 + 1] = a.y;
            As[row][c4 + 2] = a.z; As[row][c4 + 3] = a.w;
            float4 w = *(const float4*)(W + (size_t)(e0 + row) * D + k0 + c4);
            Ws[row][c4 + 0] = w.x; Ws[row][c4 + 1] = w.y;
            Ws[row][c4 + 2] = w.z; Ws[row][c4 + 3] = w.w;
        }
        __syncthreads();
        #pragma unroll
        for (int kk = 0; kk < 64; kk++) {
            float av[4], wv[4];
            #pragma unroll
            for (int i = 0; i < 4; i++) av[i] = As[ty * 4 + i][kk];
            #pragma unroll
            for (int j = 0; j < 4; j++) wv[j] = Ws[tx * 4 + j][kk];
            #pragma unroll
            for (int i = 0; i < 4; i++)
                #pragma unroll
                for (int j = 0; j < 4; j++) acc[i][j] += av[i] * wv[j];
        }
        __syncthreads();
    }
    #pragma unroll
    for (int i = 0; i < 4; i++) {
        int b = ty * 4 + i;
        #pragma unroll
        for (int j = 0; j < 4; j++) {
            int e = e0 + tx * 4 + j;
            atomicAdd(&C[(size_t)b * D + e], acc[i][j]);
        }
    }
}

// ---------------------------------------------------------------------------
// Fused: scores[b,s] = (q[b] . k[b,s]) / 32  AND  k_out[b,s,:] = k[b,s,:]
// One warp per s-row; 16 rows per 512-thread block.
// All 8 LDG.128 issued before any compute/store (MLP=8).
__global__ void scores_copy_kernel(const float* __restrict__ prev_k,
                                   float* __restrict__ k_out) {
    int b = blockIdx.x;
    __shared__ float4 qs[D / 4];
    for (int i = threadIdx.x; i < D / 4; i += blockDim.x)
        qs[i] = ((const float4*)(g_q + b * D))[i];
    __syncthreads();

    int s = blockIdx.y * 16 + (threadIdx.x >> 5);
    if (s > KV) return;
    int lane = threadIdx.x & 31;

    const float4* src = (s < KV)
        ? (const float4*)(prev_k + ((size_t)b * KV + s) * D)
        : (const float4*)(g_knew + b * D);
    float4* dst = (float4*)(k_out + ((size_t)b * KV1 + s) * D);

    float4 kv[8];
    #pragma unroll
    for (int i = 0; i < 8; i++) kv[i] = __ldcs(src + lane + i * 32);

    float acc = 0.f;
    #pragma unroll
    for (int i = 0; i < 8; i++) {
        float4 qv = qs[lane + i * 32];
        acc += kv[i].x * qv.x + kv[i].y * qv.y + kv[i].z * qv.z + kv[i].w * qv.w;
        __stcs(dst + lane + i * 32, kv[i]);
    }
    #pragma unroll
    for (int o = 16; o; o >>= 1) acc += __shfl_xor_sync(0xffffffffu, acc, o);
    if (lane == 0) g_scores[b * KV1 + s] = acc * 0.03125f;   // 1/sqrt(1024)
}

// ---------------------------------------------------------------------------
// Softmax over 4097 scores per row. 1024 threads, 4 elems/thread.
__global__ void softmax_kernel() {
    int b = blockIdx.x;
    float* sc = g_scores + b * KV1;
    __shared__ float red[32];
    int tid = threadIdx.x;

    float m = -1e30f;
    for (int i = tid; i < KV1; i += 1024) m = fmaxf(m, sc[i]);
    #pragma unroll
    for (int o = 16; o; o >>= 1) m = fmaxf(m, __shfl_xor_sync(0xffffffffu, m, o));
    if ((tid & 31) == 0) red[tid >> 5] = m;
    __syncthreads();
    if (tid < 32) {
        float v = red[tid];
        #pragma unroll
        for (int o = 16; o; o >>= 1) v = fmaxf(v, __shfl_xor_sync(0xffffffffu, v, o));
        if (tid == 0) red[0] = v;
    }
    __syncthreads();
    m = red[0];
    __syncthreads();

    float sum = 0.f;
    for (int i = tid; i < KV1; i += 1024) {
        float e = __expf(sc[i] - m);
        sc[i] = e;
        sum += e;
    }
    #pragma unroll
    for (int o = 16; o; o >>= 1) sum += __shfl_xor_sync(0xffffffffu, sum, o);
    if ((tid & 31) == 0) red[tid >> 5] = sum;
    __syncthreads();
    if (tid < 32) {
        float v = red[tid];
        #pragma unroll
        for (int o = 16; o; o >>= 1) v += __shfl_xor_sync(0xffffffffu, v, o);
        if (tid == 0) red[0] = v;
    }
    __syncthreads();
    float inv = 1.0f / red[0];
    for (int i = tid; i < KV1; i += 1024) sc[i] *= inv;
}

// ---------------------------------------------------------------------------
// Fused: attn[b,d] += sum_{s in chunk} probs[b,s]*v[b,s,d]  AND copy v rows.
// Block = (b, 256-row s-chunk); 256 threads; 8-deep load batches (MLP=8).
__global__ void attn_copy_kernel(const float* __restrict__ prev_v,
                                 float* __restrict__ v_out) {
    int b = blockIdx.x;
    int s0 = blockIdx.y * 256;
    int t = threadIdx.x;
    const float* p = g_scores + b * KV1;
    __shared__ float ps[256];
    ps[t] = p[s0 + t];
    __syncthreads();

    const float4* vbase = (const float4*)(prev_v + (size_t)b * KV * D) + t;
    float4* obase = (float4*)(v_out + (size_t)b * KV1 * D) + t;

    float4 acc = make_float4(0.f, 0.f, 0.f, 0.f);
    for (int s = 0; s < 256; s += 8) {
        float4 val[8];
        #pragma unroll
        for (int j = 0; j < 8; j++)
            val[j] = __ldcs(vbase + (size_t)(s0 + s + j) * (D / 4));
        #pragma unroll
        for (int j = 0; j < 8; j++) {
            float w = ps[s + j];
            acc.x += w * val[j].x; acc.y += w * val[j].y;
            acc.z += w * val[j].z; acc.w += w * val[j].w;
            __stcs(obase + (size_t)(s0 + s + j) * (D / 4), val[j]);
        }
    }
    if (blockIdx.y == NCHUNK - 1) {              // new row s = 4096
        float4 val = ((const float4*)(g_vnew + b * D))[t];
        float w = p[KV];
        acc.x += w * val.x; acc.y += w * val.y;
        acc.z += w * val.z; acc.w += w * val.w;
        __stcs(obase + (size_t)KV * (D / 4), val);
    }
    float* ga = g_attn + b * D + t * 4;
    atomicAdd(ga + 0, acc.x);
    atomicAdd(ga + 1, acc.y);
    atomicAdd(ga + 2, acc.z);
    atomicAdd(ga + 3, acc.w);
}

// ---------------------------------------------------------------------------
extern "C" void kernel_launch(void* const* d_in, const int* in_sizes, int n_in,
                              void* d_out, int out_size) {
    const int*   x      = (const int*)d_in[0];
    const float* prev_k = (const float*)d_in[1];
    const float* prev_v = (const float*)d_in[2];
    const float* emb    = (const float*)d_in[3];
    const float* Wq     = (const float*)d_in[4];
    const float* bq     = (const float*)d_in[5];
    const float* Wk     = (const float*)d_in[6];
    const float* bk     = (const float*)d_in[7];
    const float* Wv     = (const float*)d_in[8];
    const float* bv     = (const float*)d_in[9];
    const float* Wo     = (const float*)d_in[10];
    const float* bo     = (const float*)d_in[11];

    float* out   = (float*)d_out;                       // (64, 1, 1024)
    float* k_out = out + (size_t)BATCH * D;             // (64, 4097, 1024)
    float* v_out = k_out + (size_t)BATCH * KV1 * D;     // (64, 4097, 1024)

    init_kernel<<<BATCH, 256>>>(x, emb, bq, bk, bv, bo, out);
    gemm_splitk<<<dim3(16, 8, 3), 256>>>(0, Wq, Wk, Wv, nullptr);
    scores_copy_kernel<<<dim3(BATCH, 257), 512>>>(prev_k, k_out);
    softmax_kernel<<<BATCH, 1024>>>();
    attn_copy_kernel<<<dim3(BATCH, NCHUNK), 256>>>(prev_v, v_out);
    gemm_splitk<<<dim3(16, 8, 1), 256>>>(1, Wo, nullptr, nullptr, out);
}

// round 7
// speedup vs baseline: 1.0051x; 1.0032x over previous
#include <cuda_runtime.h>
#include <cuda_bf16.h>

#define D      1024
#define BATCH  64
#define KV     4096
#define KV1    4097
#define NCHUNK 32

// Scratch (no allocations allowed) ------------------------------------------
__device__ float g_cur[BATCH * D];
__device__ float g_q[BATCH * D];
__device__ float g_knew[BATCH * D];
__device__ float g_vnew[BATCH * D];
__device__ float g_scores[BATCH * KV1];
__device__ float g_attn[BATCH * D];
__device__ float g_mx[BATCH];
__device__ float g_inv[BATCH];

// ---------------------------------------------------------------------------
__global__ void init_kernel(const int* __restrict__ x, const float* __restrict__ emb,
                            const float* __restrict__ bq, const float* __restrict__ bk,
                            const float* __restrict__ bv, const float* __restrict__ bo,
                            float* __restrict__ out) {
    int b = blockIdx.x;
    int row = x[b];
    for (int i = threadIdx.x; i < D; i += blockDim.x) {
        g_cur[b * D + i]  = emb[(size_t)row * D + i];
        g_q[b * D + i]    = bq[i];
        g_knew[b * D + i] = bk[i];
        g_vnew[b * D + i] = bv[i];
        g_attn[b * D + i] = 0.f;
        out[b * D + i]    = bo[i];
    }
}

// ---------------------------------------------------------------------------
// Split-K GEMM: C[b,e] += sum_{k in 64-slice} A[b,k] * W[e,k]
// mode 0: A=g_cur, z selects (Wq->g_q, Wk->g_knew, Wv->g_vnew), grid (16,16,3)
// mode 1: A=g_attn, W=Wa, C=Cext, grid (16,16)
__global__ void gemm_splitk(int mode, const float* __restrict__ Wa,
                            const float* __restrict__ Wb, const float* __restrict__ Wc,
                            float* __restrict__ Cext) {
    const float* A = (mode == 0) ? g_cur : g_attn;
    const float* W = (mode == 0)
        ? (blockIdx.z == 0 ? Wa : blockIdx.z == 1 ? Wb : Wc) : Wa;
    float* C = (mode == 0)
        ? (blockIdx.z == 0 ? g_q : blockIdx.z == 1 ? g_knew : g_vnew) : Cext;

    __shared__ float As[64][65];
    __shared__ float Ws[64][65];
    const int e0 = blockIdx.x * 64;
    const int k0 = blockIdx.y * 64;              // single 64-wide K slice
    const int tid = threadIdx.x;
    const int ty = tid >> 4, tx = tid & 15;
    float acc[4][4] = {};

    for (int i = tid; i < 1024; i += 256) {
        int row = i >> 4;
        int c4  = (i & 15) * 4;
        float4 a = *(const float4*)(A + (size_t)row * D + k0 + c4);
        As[row][c4 + 0] = a.x; As[row][c4 + 1] = a.y;
        As[row][c4 + 2] = a.z; As[row][c4 + 3] = a.w;
        float4 w = *(const float4*)(W + (size_t)(e0 + row) * D + k0 + c4);
        Ws[row][c4 + 0] = w.x; Ws[row][c4 + 1] = w.y;
        Ws[row][c4 + 2] = w.z; Ws[row][c4 + 3] = w.w;
    }
    __syncthreads();
    #pragma unroll
    for (int kk = 0; kk < 64; kk++) {
        float av[4], wv[4];
        #pragma unroll
        for (int i = 0; i < 4; i++) av[i] = As[ty * 4 + i][kk];
        #pragma unroll
        for (int j = 0; j < 4; j++) wv[j] = Ws[tx * 4 + j][kk];
        #pragma unroll
        for (int i = 0; i < 4; i++)
            #pragma unroll
            for (int j = 0; j < 4; j++) acc[i][j] += av[i] * wv[j];
    }
    #pragma unroll
    for (int i = 0; i < 4; i++) {
        int b = ty * 4 + i;
        #pragma unroll
        for (int j = 0; j < 4; j++) {
            int e = e0 + tx * 4 + j;
            atomicAdd(&C[(size_t)b * D + e], acc[i][j]);
        }
    }
}

// ---------------------------------------------------------------------------
// Fused: scores[b,s] = (q[b] . k[b,s]) / 32  AND  k_out[b,s,:] = k[b,s,:]
// One warp per s-row; 16 rows per 512-thread block; MLP=8 front-batched loads.
__global__ void scores_copy_kernel(const float* __restrict__ prev_k,
                                   float* __restrict__ k_out) {
    int b = blockIdx.x;
    __shared__ float4 qs[D / 4];
    for (int i = threadIdx.x; i < D / 4; i += blockDim.x)
        qs[i] = ((const float4*)(g_q + b * D))[i];
    __syncthreads();

    int s = blockIdx.y * 16 + (threadIdx.x >> 5);
    if (s > KV) return;
    int lane = threadIdx.x & 31;

    const float4* src = (s < KV)
        ? (const float4*)(prev_k + ((size_t)b * KV + s) * D)
        : (const float4*)(g_knew + b * D);
    float4* dst = (float4*)(k_out + ((size_t)b * KV1 + s) * D);

    float4 kv[8];
    #pragma unroll
    for (int i = 0; i < 8; i++) kv[i] = __ldcs(src + lane + i * 32);

    float acc = 0.f;
    #pragma unroll
    for (int i = 0; i < 8; i++) {
        float4 qv = qs[lane + i * 32];
        acc += kv[i].x * qv.x + kv[i].y * qv.y + kv[i].z * qv.z + kv[i].w * qv.w;
        __stcs(dst + lane + i * 32, kv[i]);
    }
    #pragma unroll
    for (int o = 16; o; o >>= 1) acc += __shfl_xor_sync(0xffffffffu, acc, o);
    if (lane == 0) g_scores[b * KV1 + s] = acc * 0.03125f;   // 1/sqrt(1024)
}

// ---------------------------------------------------------------------------
// Softmax stats only: m[b] = max_s score, inv[b] = 1/sum exp(score-m).
// Single read pass; probs are never materialized.
__global__ void softmax_stats_kernel() {
    int b = blockIdx.x;
    const float* sc = g_scores + b * KV1;
    __shared__ float red[32];
    int tid = threadIdx.x;

    float v0 = sc[tid];
    float v1 = sc[tid + 1024];
    float v2 = sc[tid + 2048];
    float v3 = sc[tid + 3072];
    float v4 = (tid == 0) ? sc[4096] : -1e30f;

    float m = fmaxf(fmaxf(fmaxf(v0, v1), fmaxf(v2, v3)), v4);
    #pragma unroll
    for (int o = 16; o; o >>= 1) m = fmaxf(m, __shfl_xor_sync(0xffffffffu, m, o));
    if ((tid & 31) == 0) red[tid >> 5] = m;
    __syncthreads();
    if (tid < 32) {
        float v = red[tid];
        #pragma unroll
        for (int o = 16; o; o >>= 1) v = fmaxf(v, __shfl_xor_sync(0xffffffffu, v, o));
        if (tid == 0) red[0] = v;
    }
    __syncthreads();
    m = red[0];
    __syncthreads();

    float sum = __expf(v0 - m) + __expf(v1 - m) + __expf(v2 - m) + __expf(v3 - m);
    if (tid == 0) sum += __expf(v4 - m);
    #pragma unroll
    for (int o = 16; o; o >>= 1) sum += __shfl_xor_sync(0xffffffffu, sum, o);
    if ((tid & 31) == 0) red[tid >> 5] = sum;
    __syncthreads();
    if (tid < 32) {
        float v = red[tid];
        #pragma unroll
        for (int o = 16; o; o >>= 1) v += __shfl_xor_sync(0xffffffffu, v, o);
        if (tid == 0) { g_mx[b] = m; g_inv[b] = 1.0f / v; }
    }
}

// ---------------------------------------------------------------------------
// Fused: attn[b,d] += sum_{s in chunk} softmax(s)*v[b,s,d]  AND copy v rows.
// Block = (b, 128-row s-chunk); 256 threads; probs computed on the fly.
__global__ void attn_copy_kernel(const float* __restrict__ prev_v,
                                 float* __restrict__ v_out) {
    int b = blockIdx.x;
    int s0 = blockIdx.y * 128;
    int t = threadIdx.x;
    float mx = g_mx[b];
    float inv = g_inv[b];
    const float* p = g_scores + b * KV1;
    __shared__ float ps[128];
    if (t < 128) ps[t] = __expf(p[s0 + t] - mx) * inv;
    __syncthreads();

    const float4* vbase = (const float4*)(prev_v + (size_t)b * KV * D) + t;
    float4* obase = (float4*)(v_out + (size_t)b * KV1 * D) + t;

    float4 acc = make_float4(0.f, 0.f, 0.f, 0.f);
    for (int s = 0; s < 128; s += 8) {
        float4 val[8];
        #pragma unroll
        for (int j = 0; j < 8; j++)
            val[j] = __ldcs(vbase + (size_t)(s0 + s + j) * (D / 4));
        #pragma unroll
        for (int j = 0; j < 8; j++) {
            float w = ps[s + j];
            acc.x += w * val[j].x; acc.y += w * val[j].y;
            acc.z += w * val[j].z; acc.w += w * val[j].w;
            __stcs(obase + (size_t)(s0 + s + j) * (D / 4), val[j]);
        }
    }
    if (blockIdx.y == NCHUNK - 1) {              // new row s = 4096
        float4 val = ((const float4*)(g_vnew + b * D))[t];
        float w = __expf(p[KV] - mx) * inv;
        acc.x += w * val.x; acc.y += w * val.y;
        acc.z += w * val.z; acc.w += w * val.w;
        __stcs(obase + (size_t)KV * (D / 4), val);
    }
    float* ga = g_attn + b * D + t * 4;
    atomicAdd(ga + 0, acc.x);
    atomicAdd(ga + 1, acc.y);
    atomicAdd(ga + 2, acc.z);
    atomicAdd(ga + 3, acc.w);
}

// ---------------------------------------------------------------------------
extern "C" void kernel_launch(void* const* d_in, const int* in_sizes, int n_in,
                              void* d_out, int out_size) {
    const int*   x      = (const int*)d_in[0];
    const float* prev_k = (const float*)d_in[1];
    const float* prev_v = (const float*)d_in[2];
    const float* emb    = (const float*)d_in[3];
    const float* Wq     = (const float*)d_in[4];
    const float* bq     = (const float*)d_in[5];
    const float* Wk     = (const float*)d_in[6];
    const float* bk     = (const float*)d_in[7];
    const float* Wv     = (const float*)d_in[8];
    const float* bv     = (const float*)d_in[9];
    const float* Wo     = (const float*)d_in[10];
    const float* bo     = (const float*)d_in[11];

    float* out   = (float*)d_out;                       // (64, 1, 1024)
    float* k_out = out + (size_t)BATCH * D;             // (64, 4097, 1024)
    float* v_out = k_out + (size_t)BATCH * KV1 * D;     // (64, 4097, 1024)

    init_kernel<<<BATCH, 256>>>(x, emb, bq, bk, bv, bo, out);
    gemm_splitk<<<dim3(16, 16, 3), 256>>>(0, Wq, Wk, Wv, nullptr);
    scores_copy_kernel<<<dim3(BATCH, 257), 512>>>(prev_k, k_out);
    softmax_stats_kernel<<<BATCH, 1024>>>();
    attn_copy_kernel<<<dim3(BATCH, NCHUNK), 256>>>(prev_v, v_out);
    gemm_splitk<<<dim3(16, 16, 1), 256>>>(1, Wo, nullptr, nullptr, out);
}